// round 15
// baseline (speedup 1.0000x reference)
#include <cuda_runtime.h>

// Problem constants
#define NBL 32   // B*L
#define NC  32   // channels
#define NH  128
#define NW  256
#define NJ  32   // kept W-modes
#define NP  64   // kept H-rows: {0..31, 96..127}
#define NBAT  1024          // x batches (bl*c)
#define NBATT 1056          // x + k batches

typedef unsigned long long u64;

// ---- packed fp32x2 helpers (PTX-only; ptxas never auto-fuses) ----
__device__ __forceinline__ u64 dup2(float v) {
    u64 r; asm("mov.b64 %0,{%1,%1};" : "=l"(r) : "f"(v)); return r;
}
__device__ __forceinline__ u64 pack2(float a, float b) {
    u64 r; asm("mov.b64 %0,{%1,%2};" : "=l"(r) : "f"(a), "f"(b)); return r;
}
__device__ __forceinline__ void fma2(u64 &d, u64 a, u64 b) {
    asm("fma.rn.f32x2 %0,%1,%2,%0;" : "+l"(d) : "l"(a), "l"(b));
}
__device__ __forceinline__ u64 mul2(u64 a, u64 b) {
    u64 d; asm("mul.rn.f32x2 %0,%1,%2;" : "=l"(d) : "l"(a), "l"(b)); return d;
}
__device__ __forceinline__ u64 add2(u64 a, u64 b) {
    u64 d; asm("add.rn.f32x2 %0,%1,%2;" : "=l"(d) : "l"(a), "l"(b)); return d;
}
__device__ __forceinline__ float2 up2(u64 v) {
    float2 f; asm("mov.b64 {%0,%1},%2;" : "=f"(f.x), "=f"(f.y) : "l"(v)); return f;
}

// ---------------- scratch ----------------
// T / tmp layout: [m = batch*128+h][r = comp*32+j]
// Z / G layout: [batch][p][comp][j]
// Wr / Wi layout: [mode = p*32+j][co = c*32+o]
__device__ __align__(16) float g_T  [(size_t)NBATT*NH*64];
__device__ __align__(16) float g_Z  [(size_t)NBATT*NP*2*NJ];
__device__ __align__(16) float g_G  [(size_t)NBAT*NP*2*NJ];
__device__ __align__(16) float g_tmp[(size_t)NBAT*NH*64];
__device__ __align__(16) float g_DW [NW*64];      // fwd W-DFT  [w][r]
__device__ __align__(16) float g_DI [64*NW];      // inv W c2r  [r][w]
__device__ __align__(16) float g_Wr [(size_t)NP*NJ*NC*NC];
__device__ __align__(16) float g_Wi [(size_t)NP*NJ*NC*NC];

// ---------------- weight transpose + DFT matrix init (merged) ----------------
__global__ __launch_bounds__(256) void prep_all(const float* __restrict__ w1r,
                                                const float* __restrict__ w1i,
                                                const float* __restrict__ w2r,
                                                const float* __restrict__ w2i) {
    __shared__ float tile[32][33];
    int bz = blockIdx.z;
    // DFT matrix init folded into the first 64 (bz==0, by<2) blocks
    if (bz == 0 && blockIdx.y < 2) {
        int idx = (blockIdx.y * 32 + blockIdx.x) * 256 + threadIdx.x;  // 0..16383
        if (idx < NW * 64) {
            int w = idx >> 6, r = idx & 63, comp = r >> 5, j = r & 31;
            int t = (j * w) % NW;
            float s, c; sincospif(2.0f * (float)t / (float)NW, &s, &c);
            g_DW[idx] = comp ? -s : c;
        }
        if (idx < 64 * NW) {
            int r = idx >> 8, w = idx & 255, comp = r >> 5, j = r & 31;
            int t = (j * w) % NW;
            float s, c; sincospif(2.0f * (float)t / (float)NW, &s, &c);
            float v;
            if (comp == 0) v = ((j == 0) ? 1.0f : 2.0f) * (1.0f / (float)NW) * c;
            else           v = (j == 0) ? 0.0f : (-2.0f / (float)NW) * s;
            g_DI[idx] = v;
        }
    }
    const float* src = (bz == 0) ? w1r : (bz == 1) ? w1i : (bz == 2) ? w2r : w2i;
    float* dst = ((bz & 1) ? g_Wi : g_Wr) + ((bz >> 1) ? (size_t)32 * 32 * 1024 : 0);
    int co0 = blockIdx.y * 32, ij0 = blockIdx.x * 32;
    int tx = threadIdx.x & 31, ty = threadIdx.x >> 5;
#pragma unroll
    for (int q = 0; q < 4; q++)
        tile[ty + 8 * q][tx] = src[(size_t)(co0 + ty + 8 * q) * 1024 + ij0 + tx];
    __syncthreads();
#pragma unroll
    for (int q = 0; q < 4; q++)
        dst[(size_t)(ij0 + ty + 8 * q) * 1024 + co0 + tx] = tile[tx][ty + 8 * q];
}

// ---------------- forward W-DFT, mirror-folded; 256 threads, static smem ----------------
__global__ __launch_bounds__(256) void gemm_fwd(const float* __restrict__ A0,
                                                const float* __restrict__ A1, int split,
                                                float* __restrict__ Cm) {
    __shared__ __align__(16) float2 Es2[16][130];
    __shared__ __align__(16) float2 Ds2[16][130];
    __shared__ float Bc[16][34];
    __shared__ float Bs[16][34];
    __shared__ float e128s[128];

    int by = blockIdx.x;
    const float* Ab = (by < split) ? (A0 + (size_t)by * 128 * NW)
                                   : (A1 + (size_t)(by - split) * 128 * NW);
    int t = threadIdx.x;
    int tx = t & 7, ty = t >> 3;

    if (t < 128) e128s[t] = Ab[(size_t)t * NW + 128];

    u64 acc[4][4];
#pragma unroll
    for (int i = 0; i < 4; i++)
#pragma unroll
        for (int m = 0; m < 4; m++) acc[i][m] = 0ull;

    for (int c0 = 0; c0 < 128; c0 += 16) {
        __syncthreads();
#pragma unroll
        for (int f = t; f < 16 * 32; f += 256) {
            int k = f >> 5, j = f & 31;
            int kg = c0 + k;
            float bc = g_DW[kg * 64 + j];
            Bc[k][j] = (kg == 0) ? 0.5f * bc : bc;
            Bs[k][j] = g_DW[kg * 64 + 32 + j];
        }
#pragma unroll
        for (int q = 0; q < 2; q++) {
            int f = t + 256 * q;
            int row = f >> 2, fc = f & 3;
            const float* xr = Ab + (size_t)row * NW;
            float4 v = *(const float4*)(xr + c0 + fc * 4);
            float mv[4];
#pragma unroll
            for (int e = 0; e < 4; e++) {
                int k = c0 + fc * 4 + e;
                mv[e] = xr[(256 - k) & 255];
            }
            float ve[4] = {v.x, v.y, v.z, v.w};
#pragma unroll
            for (int e = 0; e < 4; e++) {
                int kk = fc * 4 + e;
                float ev = ve[e] + mv[e];
                float dv = ve[e] - mv[e];
                Es2[kk][row] = make_float2(ev, ev);
                Ds2[kk][row] = make_float2(dv, dv);
            }
        }
        __syncthreads();
#pragma unroll
        for (int kk = 0; kk < 16; kk++) {
            u64 bc0 = *(const u64*)&Bc[kk][tx * 2];
            u64 bc1 = *(const u64*)&Bc[kk][tx * 2 + 16];
            u64 bs0 = *(const u64*)&Bs[kk][tx * 2];
            u64 bs1 = *(const u64*)&Bs[kk][tx * 2 + 16];
            const ulonglong2* pe = (const ulonglong2*)&Es2[kk][ty * 4];
            const ulonglong2* pd = (const ulonglong2*)&Ds2[kk][ty * 4];
            ulonglong2 e01 = pe[0], e23 = pe[1];
            ulonglong2 d01 = pd[0], d23 = pd[1];
            u64 aE[4] = {e01.x, e01.y, e23.x, e23.y};
            u64 aD[4] = {d01.x, d01.y, d23.x, d23.y};
#pragma unroll
            for (int i = 0; i < 4; i++) {
                fma2(acc[i][0], aE[i], bc0);
                fma2(acc[i][1], aE[i], bc1);
                fma2(acc[i][2], aD[i], bs0);
                fma2(acc[i][3], aD[i], bs1);
            }
        }
    }
    u64 PM1 = pack2(1.0f, -1.0f);
#pragma unroll
    for (int i = 0; i < 4; i++) {
        u64 e2 = dup2(e128s[ty * 4 + i]);
        fma2(acc[i][0], e2, PM1);
        fma2(acc[i][1], e2, PM1);
        float* dst = Cm + (size_t)((size_t)by * 128 + ty * 4 + i) * 64;
        *(float2*)&dst[tx * 2]      = up2(acc[i][0]);
        *(float2*)&dst[tx * 2 + 16] = up2(acc[i][1]);
        *(float2*)&dst[32 + tx * 2] = up2(acc[i][2]);
        *(float2*)&dst[48 + tx * 2] = up2(acc[i][3]);
    }
}

// ---------------- forward H-DFT v4: parity-folded (h-loop 33), recurrence twiddles ----------------
__global__ __launch_bounds__(256) void fwdH2(const float* __restrict__ Tin,
                                             float* __restrict__ Zout) {
    __shared__ __align__(16) float Ap[2][33][36];
    __shared__ __align__(16) float Am[2][33][36];
    __shared__ __align__(16) float Bp[2][33][36];
    __shared__ __align__(16) float Bm[2][33][36];
    int batch = blockIdx.x, t = threadIdx.x;
    const float* src = Tin + (size_t)batch * NH * 64;
    for (int f = t; f < 33 * 16; f += 256) {
        int r = f >> 4, c4 = (f & 15) * 4;
        int comp = c4 >> 5, cc = c4 & 31;
        float4 a  = *(const float4*)(src + r * 64 + c4);
        float4 b  = make_float4(0.f, 0.f, 0.f, 0.f);
        float4 b2 = make_float4(0.f, 0.f, 0.f, 0.f);
        if (r >= 1) {
            b  = *(const float4*)(src + (128 - r) * 64 + c4);
            b2 = *(const float4*)(src + (64 + r) * 64 + c4);
        }
        float4 a2 = *(const float4*)(src + (64 - r) * 64 + c4);
        float fsc = (r == 32) ? 0.5f : 1.0f;
        float sgn = comp ? 1.0f : -1.0f;
        float4 e   = make_float4(a.x + b.x,  a.y + b.y,  a.z + b.z,  a.w + b.w);
        float4 e2  = make_float4(a2.x + b2.x, a2.y + b2.y, a2.z + b2.z, a2.w + b2.w);
        float4 sv  = make_float4(sgn * (a.x - b.x),  sgn * (a.y - b.y),
                                 sgn * (a.z - b.z),  sgn * (a.w - b.w));
        float4 sv2 = make_float4(sgn * (a2.x - b2.x), sgn * (a2.y - b2.y),
                                 sgn * (a2.z - b2.z), sgn * (a2.w - b2.w));
        *(float4*)&Ap[comp][r][cc] = make_float4((e.x + e2.x) * fsc, (e.y + e2.y) * fsc,
                                                 (e.z + e2.z) * fsc, (e.w + e2.w) * fsc);
        *(float4*)&Am[comp][r][cc] = make_float4((e.x - e2.x) * fsc, (e.y - e2.y) * fsc,
                                                 (e.z - e2.z) * fsc, (e.w - e2.w) * fsc);
        *(float4*)&Bp[comp ^ 1][r][cc] = make_float4((sv.x - sv2.x) * fsc, (sv.y - sv2.y) * fsc,
                                                     (sv.z - sv2.z) * fsc, (sv.w - sv2.w) * fsc);
        *(float4*)&Bm[comp ^ 1][r][cc] = make_float4((sv.x + sv2.x) * fsc, (sv.y + sv2.y) * fsc,
                                                     (sv.z + sv2.z) * fsc, (sv.w + sv2.w) * fsc);
    }
    __syncthreads();

    int tx = t & 7, ty = t >> 3;
    int compo = tx >> 2, bf = (tx & 3) * 8;
    int parity = ty & 1, pg = ty >> 1;
    const float* pA = parity ? &Am[compo][0][bf] : &Ap[compo][0][bf];
    const float* pB = parity ? &Bm[compo][0][bf] : &Bp[compo][0][bf];

    u64 cd[2], sd[2], c1[2], s1[2], ns1[2];
#pragma unroll
    for (int i = 0; i < 2; i++) {
        int p = 4 * pg + 2 * i + parity;
        int row = (p < 32) ? p : 64 + p;
        float ss, cc2; sincospif((float)row * (1.0f / 64.0f), &ss, &cc2);
        c1[i] = dup2(cc2); s1[i] = dup2(ss); ns1[i] = dup2(-ss);
        cd[i] = dup2(1.0f); sd[i] = dup2(0.0f);
    }
    u64 acc[2][4];
#pragma unroll
    for (int i = 0; i < 2; i++)
#pragma unroll
        for (int m = 0; m < 4; m++) acc[i][m] = 0ull;

    for (int h = 0; h < 33; h++) {
        ulonglong2 e01 = *(const ulonglong2*)(pA + h * 36);
        ulonglong2 e23 = *(const ulonglong2*)(pA + h * 36 + 4);
        ulonglong2 d01 = *(const ulonglong2*)(pB + h * 36);
        ulonglong2 d23 = *(const ulonglong2*)(pB + h * 36 + 4);
#pragma unroll
        for (int i = 0; i < 2; i++) {
            fma2(acc[i][0], cd[i], e01.x); fma2(acc[i][1], cd[i], e01.y);
            fma2(acc[i][2], cd[i], e23.x); fma2(acc[i][3], cd[i], e23.y);
            fma2(acc[i][0], sd[i], d01.x); fma2(acc[i][1], sd[i], d01.y);
            fma2(acc[i][2], sd[i], d23.x); fma2(acc[i][3], sd[i], d23.y);
            u64 nc = mul2(cd[i], c1[i]); fma2(nc, sd[i], ns1[i]);
            u64 ns = mul2(sd[i], c1[i]); fma2(ns, cd[i], s1[i]);
            cd[i] = nc; sd[i] = ns;
        }
    }
#pragma unroll
    for (int i = 0; i < 2; i++) {
        int p = 4 * pg + 2 * i + parity;
        float* dst = Zout + (((size_t)batch * NP + p) * 2 + compo) * NJ + (tx & 3) * 8;
        *(ulonglong2*)dst       = make_ulonglong2(acc[i][0], acc[i][1]);
        *(ulonglong2*)(dst + 4) = make_ulonglong2(acc[i][2], acc[i][3]);
    }
}

// ---------------- per-mode channel mix v3: 256 threads (2bl x 2o), mode-major weights ----------------
__global__ __launch_bounds__(256) void mix2() {
    int blk = blockIdx.x;
    int p = blk >> 4, jp = blk & 15;
    int mode0 = p * 32 + jp * 2;
    __shared__ float2 s_zkr[NC][33];
    __shared__ float2 s_zki[NC][33];
    __shared__ float2 s_wr [NC][33];
    __shared__ float2 s_wi [NC][33];
    __shared__ float2 s_nwi[NC][33];
    int t = threadIdx.x;
    for (int e = t; e < 1024; e += 256) {
        int c = e >> 5, bl = e & 31;
        int blc = bl * NC + c;
        const float* zb = g_Z + (((size_t)blc * NP + p) * 2) * NJ + jp * 2;
        float2 zr = *(const float2*)zb;
        float2 zi = *(const float2*)(zb + NJ);
        const float* kb = g_Z + (((size_t)(NBAT + c) * NP + p) * 2) * NJ + jp * 2;
        float2 kr = *(const float2*)kb;
        float2 ki = *(const float2*)(kb + NJ);
        s_zkr[c][bl] = make_float2(zr.x * kr.x - zi.x * ki.x, zr.y * kr.y - zi.y * ki.y);
        s_zki[c][bl] = make_float2(zr.x * ki.x + zi.x * kr.x, zr.y * ki.y + zi.y * kr.y);
    }
    for (int e = t; e < 1024; e += 256) {
        int c = e >> 5, o = e & 31;
        float wr0 = g_Wr[(size_t)mode0 * 1024 + e];
        float wr1 = g_Wr[(size_t)(mode0 + 1) * 1024 + e];
        float wi0 = g_Wi[(size_t)mode0 * 1024 + e];
        float wi1 = g_Wi[(size_t)(mode0 + 1) * 1024 + e];
        s_wr[c][o] = make_float2(wr0, wr1);
        s_wi[c][o] = make_float2(wi0, wi1);
        s_nwi[c][o] = make_float2(-wi0, -wi1);
    }
    __syncthreads();

    int op = t & 15, blp = t >> 4;
    u64 ar[2][2], ai[2][2];
#pragma unroll
    for (int a = 0; a < 2; a++)
#pragma unroll
        for (int b = 0; b < 2; b++) { ar[a][b] = 0ull; ai[a][b] = 0ull; }

#pragma unroll 4
    for (int c = 0; c < NC; c++) {
        u64 xr[2], xi[2], wr2[2], wi2[2], nw2[2];
#pragma unroll
        for (int a = 0; a < 2; a++) {
            xr[a] = *(const u64*)&s_zkr[c][blp * 2 + a];
            xi[a] = *(const u64*)&s_zki[c][blp * 2 + a];
        }
#pragma unroll
        for (int b = 0; b < 2; b++) {
            wr2[b] = *(const u64*)&s_wr [c][op * 2 + b];
            wi2[b] = *(const u64*)&s_wi [c][op * 2 + b];
            nw2[b] = *(const u64*)&s_nwi[c][op * 2 + b];
        }
#pragma unroll
        for (int a = 0; a < 2; a++)
#pragma unroll
            for (int b = 0; b < 2; b++) {
                fma2(ar[a][b], xr[a], wr2[b]); fma2(ar[a][b], xi[a], nw2[b]);
                fma2(ai[a][b], xi[a], wr2[b]); fma2(ai[a][b], xr[a], wi2[b]);
            }
    }
#pragma unroll
    for (int a = 0; a < 2; a++)
#pragma unroll
        for (int b = 0; b < 2; b++) {
            int blc = (blp * 2 + a) * NC + op * 2 + b;
            float* gb = g_G + (((size_t)blc * NP + p) * 2) * NJ + jp * 2;
            *(float2*)gb        = up2(ar[a][b]);
            *(float2*)(gb + NJ) = up2(ai[a][b]);
        }
}

// ---------------- inverse H-DFT v3: output-pair fold (h & 128-h), C/S split ----------------
// C = sum_r cd.E, S = sum_r sd.D;  tmp[h]=(C+S)/128, tmp[128-h]=(C-S)/128.
// Units u = 2ty+i (0..63): h_lo=u, h_hi=128-u (u=0: hi skipped).  h=64 via tail sum.
__global__ __launch_bounds__(256) void invH2() {
    __shared__ __align__(16) float SE[2][33][36];
    __shared__ __align__(16) float SD[2][33][36];
    int blo = blockIdx.x, t = threadIdx.x;
    const float* src = g_G + (size_t)blo * NP * 64;
    for (int f = t; f < 33 * 16; f += 256) {
        int r = f >> 4, c4 = (f & 15) * 4;
        int comp = c4 >> 5, cc = c4 & 31;
        float4 a = *(const float4*)(src + r * 64 + c4);
        float4 e, d;
        if (r == 0) {
            e = a; d = make_float4(0.f, 0.f, 0.f, 0.f);
        } else if (r == 32) {
            e = a;
            if (comp == 0) d = make_float4(-a.x, -a.y, -a.z, -a.w);
            else           d = a;
        } else {
            float4 b = *(const float4*)(src + (64 - r) * 64 + c4);
            e = make_float4(a.x + b.x, a.y + b.y, a.z + b.z, a.w + b.w);
            if (comp == 0) d = make_float4(a.x - b.x, a.y - b.y, a.z - b.z, a.w - b.w);
            else           d = make_float4(b.x - a.x, b.y - a.y, b.z - a.z, b.w - a.w);
        }
        *(float4*)&SE[comp][r][cc] = e;
        *(float4*)&SD[comp ^ 1][r][cc] = d;
    }
    __syncthreads();

    int tx = t & 7, ty = t >> 3;
    int compo = tx >> 2, bf = (tx & 3) * 8;
    const float* pe = &SE[compo][0][bf];
    const float* pd = &SD[compo][0][bf];

    u64 cd[2], sd[2], c1[2], s1[2], ns1[2];
#pragma unroll
    for (int i = 0; i < 2; i++) {
        int u = ty * 2 + i;                 // h_lo
        float ss, cc2; sincospif((float)u * (1.0f / 64.0f), &ss, &cc2);
        c1[i] = dup2(cc2); s1[i] = dup2(ss); ns1[i] = dup2(-ss);
        cd[i] = dup2(1.0f); sd[i] = dup2(0.0f);
    }
    u64 Cs[2][4], Ss[2][4];
#pragma unroll
    for (int i = 0; i < 2; i++)
#pragma unroll
        for (int m = 0; m < 4; m++) { Cs[i][m] = 0ull; Ss[i][m] = 0ull; }

    for (int r = 0; r < 33; r++) {
        ulonglong2 e01 = *(const ulonglong2*)(pe + r * 36);
        ulonglong2 e23 = *(const ulonglong2*)(pe + r * 36 + 4);
        ulonglong2 d01 = *(const ulonglong2*)(pd + r * 36);
        ulonglong2 d23 = *(const ulonglong2*)(pd + r * 36 + 4);
#pragma unroll
        for (int i = 0; i < 2; i++) {
            fma2(Cs[i][0], cd[i], e01.x); fma2(Cs[i][1], cd[i], e01.y);
            fma2(Cs[i][2], cd[i], e23.x); fma2(Cs[i][3], cd[i], e23.y);
            fma2(Ss[i][0], sd[i], d01.x); fma2(Ss[i][1], sd[i], d01.y);
            fma2(Ss[i][2], sd[i], d23.x); fma2(Ss[i][3], sd[i], d23.y);
            u64 nc = mul2(cd[i], c1[i]); fma2(nc, sd[i], ns1[i]);
            u64 ns = mul2(sd[i], c1[i]); fma2(ns, cd[i], s1[i]);
            cd[i] = nc; sd[i] = ns;
        }
    }
    u64 sc = dup2(1.0f / 128.0f);
    int jb = compo * 32 + (tx & 3) * 8;
#pragma unroll
    for (int i = 0; i < 2; i++) {
        int u = ty * 2 + i;
        u64 lo[4], hi[4];
#pragma unroll
        for (int m = 0; m < 4; m++) {
            lo[m] = mul2(add2(Cs[i][m], Ss[i][m]), sc);
            u64 diff = Cs[i][m]; fma2(diff, dup2(-1.0f), Ss[i][m]);
            hi[m] = mul2(diff, sc);
        }
        float* dlo = g_tmp + ((size_t)blo * NH + u) * 64 + jb;
        *(ulonglong2*)dlo       = make_ulonglong2(lo[0], lo[1]);
        *(ulonglong2*)(dlo + 4) = make_ulonglong2(lo[2], lo[3]);
        if (u > 0) {
            float* dhi = g_tmp + ((size_t)blo * NH + (128 - u)) * 64 + jb;
            *(ulonglong2*)dhi       = make_ulonglong2(hi[0], hi[1]);
            *(ulonglong2*)(dhi + 4) = make_ulonglong2(hi[2], hi[3]);
        }
    }
    // h=64 tail: tmp[64][comp*32+j] = (1/128) * sum_r (-1)^r * SE[comp][r][j]
    if (t < 64) {
        int comp = t >> 5, j = t & 31;
        float s = 0.0f;
#pragma unroll
        for (int r = 0; r < 33; r++) {
            float v = SE[comp][r][j];
            s += (r & 1) ? -v : v;
        }
        g_tmp[((size_t)blo * NH + 64) * 64 + comp * 32 + j] = s * (1.0f / 128.0f);
    }
}

// ---------------- inverse W c2r, mirror-folded ----------------
__global__ __launch_bounds__(256, 2) void gemm_inv(float* __restrict__ out) {
    extern __shared__ __align__(16) float sm[];
    float2* Rr2 = (float2*)sm;               // [32][130]
    float2* Ri2 = Rr2 + 32 * 130;            // [32][130]
    float*  Bc  = (float*)(Ri2 + 32 * 130);  // [32][68]
    float*  Bs  = Bc + 32 * 68;              // [32][68]

    int bx = blockIdx.x;
    int by = blockIdx.y;
    int t = threadIdx.x;
    int tx = t & 15, ty = t >> 4;

    const float* src = g_tmp + (size_t)by * 128 * 64;
#pragma unroll
    for (int q = 0; q < 8; q++) {
        int f = t + 256 * q;
        int row = f >> 4, fc = f & 15;
        float4 v = *(const float4*)(src + (size_t)row * 64 + fc * 4);
        float2* dst = (fc < 8) ? Rr2 : Ri2;
        int kb = (fc & 7) * 4;
        dst[(kb + 0) * 130 + row] = make_float2(v.x, v.x);
        dst[(kb + 1) * 130 + row] = make_float2(v.y, v.y);
        dst[(kb + 2) * 130 + row] = make_float2(v.z, v.z);
        dst[(kb + 3) * 130 + row] = make_float2(v.w, v.w);
    }
#pragma unroll
    for (int q = 0; q < 4; q++) {
        int f = t + 256 * q;
        int arr = f >> 9, rem = f & 511;
        int k = rem >> 4, wl4 = (rem & 15) * 4;
        float4 v = *(const float4*)(g_DI + (size_t)(arr * 32 + k) * 256 + bx * 64 + wl4);
        float* dst = arr ? Bs : Bc;
        *(float4*)&dst[k * 68 + wl4] = v;
    }
    __syncthreads();

    u64 Cc[8][2], Csv[8][2];
#pragma unroll
    for (int i = 0; i < 8; i++)
#pragma unroll
        for (int m = 0; m < 2; m++) { Cc[i][m] = 0ull; Csv[i][m] = 0ull; }

#pragma unroll 8
    for (int k = 0; k < 32; k++) {
        ulonglong2 bc = *(const ulonglong2*)&Bc[k * 68 + tx * 4];
        ulonglong2 bs = *(const ulonglong2*)&Bs[k * 68 + tx * 4];
        const ulonglong2* pr = (const ulonglong2*)&Rr2[k * 130 + ty * 8];
        const ulonglong2* pi = (const ulonglong2*)&Ri2[k * 130 + ty * 8];
        ulonglong2 r01 = pr[0], r23 = pr[1], r45 = pr[2], r67 = pr[3];
        ulonglong2 i01 = pi[0], i23 = pi[1], i45 = pi[2], i67 = pi[3];
        u64 aR[8] = {r01.x, r01.y, r23.x, r23.y, r45.x, r45.y, r67.x, r67.y};
        u64 aI[8] = {i01.x, i01.y, i23.x, i23.y, i45.x, i45.y, i67.x, i67.y};
#pragma unroll
        for (int i = 0; i < 8; i++) {
            fma2(Cc[i][0], aR[i], bc.x);
            fma2(Cc[i][1], aR[i], bc.y);
            fma2(Csv[i][0], aI[i], bs.x);
            fma2(Csv[i][1], aI[i], bs.y);
        }
    }
    u64 P1 = dup2(1.0f), N1 = dup2(-1.0f);
#pragma unroll
    for (int i = 0; i < 8; i++) {
        float* ob = out + (size_t)((size_t)by * 128 + ty * 8 + i) * 256;
#pragma unroll
        for (int m = 0; m < 2; m++) {
            int w0 = bx * 64 + tx * 4 + m * 2;
            u64 lo = Cc[i][m]; fma2(lo, P1, Csv[i][m]);
            u64 hi = Cc[i][m]; fma2(hi, N1, Csv[i][m]);
            *(float2*)&ob[w0] = up2(lo);
            float2 hf = up2(hi);
            if (w0 > 0) ob[256 - w0] = hf.x;
            ob[255 - w0] = hf.y;
        }
    }
}

// ---------------- out[:,128] = Tr . coef ----------------
__global__ __launch_bounds__(256) void out128(float* __restrict__ out) {
    int row = blockIdx.x * 256 + threadIdx.x;
    const float* tr = g_tmp + (size_t)row * 64;
    const float sc = 2.0f / 256.0f;
    float s = 0.0f;
#pragma unroll
    for (int q = 0; q < 8; q++) {
        float4 v = *(const float4*)(tr + q * 4);
        float x0 = (q == 0) ? 0.5f * v.x : v.x;
        s += (x0 - v.y) + (v.z - v.w);
    }
    out[(size_t)row * 256 + 128] = s * sc;
}

// ---------------- host launcher ----------------
extern "C" void kernel_launch(void* const* d_in, const int* in_sizes, int n_in,
                              void* d_out, int out_size) {
    const float* x   = (const float*)d_in[0];
    const float* k   = (const float*)d_in[1];
    const float* w1r = (const float*)d_in[2];
    const float* w1i = (const float*)d_in[3];
    const float* w2r = (const float*)d_in[4];
    const float* w2i = (const float*)d_in[5];
    float* out = (float*)d_out;
    (void)in_sizes; (void)n_in; (void)out_size;

    void *pT, *pZ;
    cudaGetSymbolAddress(&pT, g_T);
    cudaGetSymbolAddress(&pZ, g_Z);

    const int INV_SMEM = (32 * 130 * 2 * 2 + 32 * 68 * 2) * 4;          // 83968 B
    cudaFuncSetAttribute(gemm_inv, cudaFuncAttributeMaxDynamicSharedMemorySize, INV_SMEM);
    // No carveout attributes (R11: they starve L1 for neighboring kernels).

    prep_all<<<dim3(32, 32, 4), 256>>>(w1r, w1i, w2r, w2i);

    // forward W-DFT (mirror-folded) over x + k row-blocks
    gemm_fwd<<<NBATT, 256>>>(x, k, NBAT, (float*)pT);

    // forward H-DFT (parity-folded, 33 iters)
    fwdH2<<<NBATT, 256>>>((const float*)pT, (float*)pZ);

    // per-mode conv + channel mix
    mix2<<<NP * 16, 256>>>();

    // inverse H-DFT (output-pair folded, C/S split)
    invH2<<<NBAT, 256>>>();

    // inverse W c2r (mirror-folded) -> out, plus the w=128 column
    gemm_inv<<<dim3(2, NBAT), 256, INV_SMEM>>>(out);
    out128<<<512, 256>>>(out);
}

// round 16
// speedup vs baseline: 1.0662x; 1.0662x over previous
#include <cuda_runtime.h>

// Problem constants
#define NBL 32   // B*L
#define NC  32   // channels
#define NH  128
#define NW  256
#define NJ  32   // kept W-modes
#define NP  64   // kept H-rows: {0..31, 96..127}
#define NBAT  1024          // x batches (bl*c)
#define NBATT 1056          // x + k batches

typedef unsigned long long u64;

// ---- packed fp32x2 helpers (PTX-only; ptxas never auto-fuses) ----
__device__ __forceinline__ u64 dup2(float v) {
    u64 r; asm("mov.b64 %0,{%1,%1};" : "=l"(r) : "f"(v)); return r;
}
__device__ __forceinline__ u64 pack2(float a, float b) {
    u64 r; asm("mov.b64 %0,{%1,%2};" : "=l"(r) : "f"(a), "f"(b)); return r;
}
__device__ __forceinline__ void fma2(u64 &d, u64 a, u64 b) {
    asm("fma.rn.f32x2 %0,%1,%2,%0;" : "+l"(d) : "l"(a), "l"(b));
}
__device__ __forceinline__ u64 mul2(u64 a, u64 b) {
    u64 d; asm("mul.rn.f32x2 %0,%1,%2;" : "=l"(d) : "l"(a), "l"(b)); return d;
}
__device__ __forceinline__ u64 add2(u64 a, u64 b) {
    u64 d; asm("add.rn.f32x2 %0,%1,%2;" : "=l"(d) : "l"(a), "l"(b)); return d;
}
__device__ __forceinline__ float2 up2(u64 v) {
    float2 f; asm("mov.b64 {%0,%1},%2;" : "=f"(f.x), "=f"(f.y) : "l"(v)); return f;
}

// ---------------- scratch ----------------
// T / tmp layout: [m = batch*128+h][r = comp*32+j]
// Z layout: [batch][p][comp][j]  (batch-major)
// Zm layout: [mode2 = p*64+comp*32+j][blc 0..1055]  (mode-major, for mix2)
// G layout: [batch][p][comp][j]
// Wr / Wi layout: [mode = p*32+j][co = c*32+o]
__device__ __align__(16) float g_T  [(size_t)NBATT*NH*64];
__device__ __align__(16) float g_Z  [(size_t)NBATT*NP*2*NJ];
__device__ __align__(16) float g_Zm [(size_t)NP*2*NJ*NBATT];
__device__ __align__(16) float g_G  [(size_t)NBAT*NP*2*NJ];
__device__ __align__(16) float g_tmp[(size_t)NBAT*NH*64];
__device__ __align__(16) float g_DW [NW*64];      // fwd W-DFT  [w][r]
__device__ __align__(16) float g_DI [64*NW];      // inv W c2r  [r][w]
__device__ __align__(16) float g_Wr [(size_t)NP*NJ*NC*NC];
__device__ __align__(16) float g_Wi [(size_t)NP*NJ*NC*NC];

// ---------------- weight transpose + DFT matrix init (merged) ----------------
__global__ __launch_bounds__(256) void prep_all(const float* __restrict__ w1r,
                                                const float* __restrict__ w1i,
                                                const float* __restrict__ w2r,
                                                const float* __restrict__ w2i) {
    __shared__ float tile[32][33];
    int bz = blockIdx.z;
    if (bz == 0 && blockIdx.y < 2) {
        int idx = (blockIdx.y * 32 + blockIdx.x) * 256 + threadIdx.x;  // 0..16383
        if (idx < NW * 64) {
            int w = idx >> 6, r = idx & 63, comp = r >> 5, j = r & 31;
            int t = (j * w) % NW;
            float s, c; sincospif(2.0f * (float)t / (float)NW, &s, &c);
            g_DW[idx] = comp ? -s : c;
        }
        if (idx < 64 * NW) {
            int r = idx >> 8, w = idx & 255, comp = r >> 5, j = r & 31;
            int t = (j * w) % NW;
            float s, c; sincospif(2.0f * (float)t / (float)NW, &s, &c);
            float v;
            if (comp == 0) v = ((j == 0) ? 1.0f : 2.0f) * (1.0f / (float)NW) * c;
            else           v = (j == 0) ? 0.0f : (-2.0f / (float)NW) * s;
            g_DI[idx] = v;
        }
    }
    const float* src = (bz == 0) ? w1r : (bz == 1) ? w1i : (bz == 2) ? w2r : w2i;
    float* dst = ((bz & 1) ? g_Wi : g_Wr) + ((bz >> 1) ? (size_t)32 * 32 * 1024 : 0);
    int co0 = blockIdx.y * 32, ij0 = blockIdx.x * 32;
    int tx = threadIdx.x & 31, ty = threadIdx.x >> 5;
#pragma unroll
    for (int q = 0; q < 4; q++)
        tile[ty + 8 * q][tx] = src[(size_t)(co0 + ty + 8 * q) * 1024 + ij0 + tx];
    __syncthreads();
#pragma unroll
    for (int q = 0; q < 4; q++)
        dst[(size_t)(ij0 + ty + 8 * q) * 1024 + co0 + tx] = tile[tx][ty + 8 * q];
}

// ---------------- forward W-DFT, mirror-folded; 256 threads, static smem ----------------
__global__ __launch_bounds__(256) void gemm_fwd(const float* __restrict__ A0,
                                                const float* __restrict__ A1, int split,
                                                float* __restrict__ Cm) {
    __shared__ __align__(16) float2 Es2[16][130];
    __shared__ __align__(16) float2 Ds2[16][130];
    __shared__ float Bc[16][34];
    __shared__ float Bs[16][34];
    __shared__ float e128s[128];

    int by = blockIdx.x;
    const float* Ab = (by < split) ? (A0 + (size_t)by * 128 * NW)
                                   : (A1 + (size_t)(by - split) * 128 * NW);
    int t = threadIdx.x;
    int tx = t & 7, ty = t >> 3;

    if (t < 128) e128s[t] = Ab[(size_t)t * NW + 128];

    u64 acc[4][4];
#pragma unroll
    for (int i = 0; i < 4; i++)
#pragma unroll
        for (int m = 0; m < 4; m++) acc[i][m] = 0ull;

    for (int c0 = 0; c0 < 128; c0 += 16) {
        __syncthreads();
#pragma unroll
        for (int f = t; f < 16 * 32; f += 256) {
            int k = f >> 5, j = f & 31;
            int kg = c0 + k;
            float bc = g_DW[kg * 64 + j];
            Bc[k][j] = (kg == 0) ? 0.5f * bc : bc;
            Bs[k][j] = g_DW[kg * 64 + 32 + j];
        }
#pragma unroll
        for (int q = 0; q < 2; q++) {
            int f = t + 256 * q;
            int row = f >> 2, fc = f & 3;
            const float* xr = Ab + (size_t)row * NW;
            float4 v = *(const float4*)(xr + c0 + fc * 4);
            float mv[4];
#pragma unroll
            for (int e = 0; e < 4; e++) {
                int k = c0 + fc * 4 + e;
                mv[e] = xr[(256 - k) & 255];
            }
            float ve[4] = {v.x, v.y, v.z, v.w};
#pragma unroll
            for (int e = 0; e < 4; e++) {
                int kk = fc * 4 + e;
                float ev = ve[e] + mv[e];
                float dv = ve[e] - mv[e];
                Es2[kk][row] = make_float2(ev, ev);
                Ds2[kk][row] = make_float2(dv, dv);
            }
        }
        __syncthreads();
#pragma unroll
        for (int kk = 0; kk < 16; kk++) {
            u64 bc0 = *(const u64*)&Bc[kk][tx * 2];
            u64 bc1 = *(const u64*)&Bc[kk][tx * 2 + 16];
            u64 bs0 = *(const u64*)&Bs[kk][tx * 2];
            u64 bs1 = *(const u64*)&Bs[kk][tx * 2 + 16];
            const ulonglong2* pe = (const ulonglong2*)&Es2[kk][ty * 4];
            const ulonglong2* pd = (const ulonglong2*)&Ds2[kk][ty * 4];
            ulonglong2 e01 = pe[0], e23 = pe[1];
            ulonglong2 d01 = pd[0], d23 = pd[1];
            u64 aE[4] = {e01.x, e01.y, e23.x, e23.y};
            u64 aD[4] = {d01.x, d01.y, d23.x, d23.y};
#pragma unroll
            for (int i = 0; i < 4; i++) {
                fma2(acc[i][0], aE[i], bc0);
                fma2(acc[i][1], aE[i], bc1);
                fma2(acc[i][2], aD[i], bs0);
                fma2(acc[i][3], aD[i], bs1);
            }
        }
    }
    u64 PM1 = pack2(1.0f, -1.0f);
#pragma unroll
    for (int i = 0; i < 4; i++) {
        u64 e2 = dup2(e128s[ty * 4 + i]);
        fma2(acc[i][0], e2, PM1);
        fma2(acc[i][1], e2, PM1);
        float* dst = Cm + (size_t)((size_t)by * 128 + ty * 4 + i) * 64;
        *(float2*)&dst[tx * 2]      = up2(acc[i][0]);
        *(float2*)&dst[tx * 2 + 16] = up2(acc[i][1]);
        *(float2*)&dst[32 + tx * 2] = up2(acc[i][2]);
        *(float2*)&dst[48 + tx * 2] = up2(acc[i][3]);
    }
}

// ---------------- forward H-DFT v4: parity-folded (h-loop 33), recurrence twiddles ----------------
__global__ __launch_bounds__(256) void fwdH2(const float* __restrict__ Tin,
                                             float* __restrict__ Zout) {
    __shared__ __align__(16) float Ap[2][33][36];
    __shared__ __align__(16) float Am[2][33][36];
    __shared__ __align__(16) float Bp[2][33][36];
    __shared__ __align__(16) float Bm[2][33][36];
    int batch = blockIdx.x, t = threadIdx.x;
    const float* src = Tin + (size_t)batch * NH * 64;
    for (int f = t; f < 33 * 16; f += 256) {
        int r = f >> 4, c4 = (f & 15) * 4;
        int comp = c4 >> 5, cc = c4 & 31;
        float4 a  = *(const float4*)(src + r * 64 + c4);
        float4 b  = make_float4(0.f, 0.f, 0.f, 0.f);
        float4 b2 = make_float4(0.f, 0.f, 0.f, 0.f);
        if (r >= 1) {
            b  = *(const float4*)(src + (128 - r) * 64 + c4);
            b2 = *(const float4*)(src + (64 + r) * 64 + c4);
        }
        float4 a2 = *(const float4*)(src + (64 - r) * 64 + c4);
        float fsc = (r == 32) ? 0.5f : 1.0f;
        float sgn = comp ? 1.0f : -1.0f;
        float4 e   = make_float4(a.x + b.x,  a.y + b.y,  a.z + b.z,  a.w + b.w);
        float4 e2  = make_float4(a2.x + b2.x, a2.y + b2.y, a2.z + b2.z, a2.w + b2.w);
        float4 sv  = make_float4(sgn * (a.x - b.x),  sgn * (a.y - b.y),
                                 sgn * (a.z - b.z),  sgn * (a.w - b.w));
        float4 sv2 = make_float4(sgn * (a2.x - b2.x), sgn * (a2.y - b2.y),
                                 sgn * (a2.z - b2.z), sgn * (a2.w - b2.w));
        *(float4*)&Ap[comp][r][cc] = make_float4((e.x + e2.x) * fsc, (e.y + e2.y) * fsc,
                                                 (e.z + e2.z) * fsc, (e.w + e2.w) * fsc);
        *(float4*)&Am[comp][r][cc] = make_float4((e.x - e2.x) * fsc, (e.y - e2.y) * fsc,
                                                 (e.z - e2.z) * fsc, (e.w - e2.w) * fsc);
        *(float4*)&Bp[comp ^ 1][r][cc] = make_float4((sv.x - sv2.x) * fsc, (sv.y - sv2.y) * fsc,
                                                     (sv.z - sv2.z) * fsc, (sv.w - sv2.w) * fsc);
        *(float4*)&Bm[comp ^ 1][r][cc] = make_float4((sv.x + sv2.x) * fsc, (sv.y + sv2.y) * fsc,
                                                     (sv.z + sv2.z) * fsc, (sv.w + sv2.w) * fsc);
    }
    __syncthreads();

    int tx = t & 7, ty = t >> 3;
    int compo = tx >> 2, bf = (tx & 3) * 8;
    int parity = ty & 1, pg = ty >> 1;
    const float* pA = parity ? &Am[compo][0][bf] : &Ap[compo][0][bf];
    const float* pB = parity ? &Bm[compo][0][bf] : &Bp[compo][0][bf];

    u64 cd[2], sd[2], c1[2], s1[2], ns1[2];
#pragma unroll
    for (int i = 0; i < 2; i++) {
        int p = 4 * pg + 2 * i + parity;
        int row = (p < 32) ? p : 64 + p;
        float ss, cc2; sincospif((float)row * (1.0f / 64.0f), &ss, &cc2);
        c1[i] = dup2(cc2); s1[i] = dup2(ss); ns1[i] = dup2(-ss);
        cd[i] = dup2(1.0f); sd[i] = dup2(0.0f);
    }
    u64 acc[2][4];
#pragma unroll
    for (int i = 0; i < 2; i++)
#pragma unroll
        for (int m = 0; m < 4; m++) acc[i][m] = 0ull;

    for (int h = 0; h < 33; h++) {
        ulonglong2 e01 = *(const ulonglong2*)(pA + h * 36);
        ulonglong2 e23 = *(const ulonglong2*)(pA + h * 36 + 4);
        ulonglong2 d01 = *(const ulonglong2*)(pB + h * 36);
        ulonglong2 d23 = *(const ulonglong2*)(pB + h * 36 + 4);
#pragma unroll
        for (int i = 0; i < 2; i++) {
            fma2(acc[i][0], cd[i], e01.x); fma2(acc[i][1], cd[i], e01.y);
            fma2(acc[i][2], cd[i], e23.x); fma2(acc[i][3], cd[i], e23.y);
            fma2(acc[i][0], sd[i], d01.x); fma2(acc[i][1], sd[i], d01.y);
            fma2(acc[i][2], sd[i], d23.x); fma2(acc[i][3], sd[i], d23.y);
            u64 nc = mul2(cd[i], c1[i]); fma2(nc, sd[i], ns1[i]);
            u64 ns = mul2(sd[i], c1[i]); fma2(ns, cd[i], s1[i]);
            cd[i] = nc; sd[i] = ns;
        }
    }
#pragma unroll
    for (int i = 0; i < 2; i++) {
        int p = 4 * pg + 2 * i + parity;
        float* dst = Zout + (((size_t)batch * NP + p) * 2 + compo) * NJ + (tx & 3) * 8;
        *(ulonglong2*)dst       = make_ulonglong2(acc[i][0], acc[i][1]);
        *(ulonglong2*)(dst + 4) = make_ulonglong2(acc[i][2], acc[i][3]);
    }
}

// ---------------- Z transpose: [blc 1056][mode 4096] -> Zm[mode][blc] ----------------
__global__ __launch_bounds__(256) void zT() {
    __shared__ float tile[32][33];
    int r0 = blockIdx.x * 32;      // mode 0..4095
    int b0 = blockIdx.y * 32;      // blc  0..1055
    int tx = threadIdx.x & 31, ty = threadIdx.x >> 5;
#pragma unroll
    for (int q = 0; q < 4; q++)
        tile[ty + 8 * q][tx] = g_Z[(size_t)(b0 + ty + 8 * q) * 4096 + r0 + tx];
    __syncthreads();
#pragma unroll
    for (int q = 0; q < 4; q++)
        g_Zm[(size_t)(r0 + ty + 8 * q) * NBATT + b0 + tx] = tile[tx][ty + 8 * q];
}

// ---------------- per-mode channel mix v4: coalesced mode-major z loads ----------------
__global__ __launch_bounds__(256) void mix2() {
    int blk = blockIdx.x;
    int p = blk >> 4, jp = blk & 15;
    int mode0 = p * 32 + jp * 2;
    __shared__ float2 s_zkr[NC][33];
    __shared__ float2 s_zki[NC][33];
    __shared__ float2 s_wr [NC][33];
    __shared__ float2 s_wi [NC][33];
    __shared__ float2 s_nwi[NC][33];
    int t = threadIdx.x;
    // Zm rows for (comp, jj): r = p*64 + comp*32 + jp*2 + jj
    const float* z00 = g_Zm + (size_t)(p * 64 + 0 * 32 + jp * 2 + 0) * NBATT;
    const float* z01 = g_Zm + (size_t)(p * 64 + 0 * 32 + jp * 2 + 1) * NBATT;
    const float* z10 = g_Zm + (size_t)(p * 64 + 1 * 32 + jp * 2 + 0) * NBATT;
    const float* z11 = g_Zm + (size_t)(p * 64 + 1 * 32 + jp * 2 + 1) * NBATT;
    for (int e = t; e < 1024; e += 256) {      // e = blc = bl*32 + c (coalesced!)
        int c = e & 31, bl = e >> 5;
        float zr0 = z00[e], zr1 = z01[e];
        float zi0 = z10[e], zi1 = z11[e];
        float kr0 = z00[1024 + c], kr1 = z01[1024 + c];
        float ki0 = z10[1024 + c], ki1 = z11[1024 + c];
        s_zkr[c][bl] = make_float2(zr0 * kr0 - zi0 * ki0, zr1 * kr1 - zi1 * ki1);
        s_zki[c][bl] = make_float2(zr0 * ki0 + zi0 * kr0, zr1 * ki1 + zi1 * kr1);
    }
    for (int e = t; e < 1024; e += 256) {
        int c = e >> 5, o = e & 31;
        float wr0 = g_Wr[(size_t)mode0 * 1024 + e];
        float wr1 = g_Wr[(size_t)(mode0 + 1) * 1024 + e];
        float wi0 = g_Wi[(size_t)mode0 * 1024 + e];
        float wi1 = g_Wi[(size_t)(mode0 + 1) * 1024 + e];
        s_wr[c][o] = make_float2(wr0, wr1);
        s_wi[c][o] = make_float2(wi0, wi1);
        s_nwi[c][o] = make_float2(-wi0, -wi1);
    }
    __syncthreads();

    int op = t & 15, blp = t >> 4;
    u64 ar[2][2], ai[2][2];
#pragma unroll
    for (int a = 0; a < 2; a++)
#pragma unroll
        for (int b = 0; b < 2; b++) { ar[a][b] = 0ull; ai[a][b] = 0ull; }

#pragma unroll 4
    for (int c = 0; c < NC; c++) {
        u64 xr[2], xi[2], wr2[2], wi2[2], nw2[2];
#pragma unroll
        for (int a = 0; a < 2; a++) {
            xr[a] = *(const u64*)&s_zkr[c][blp * 2 + a];
            xi[a] = *(const u64*)&s_zki[c][blp * 2 + a];
        }
#pragma unroll
        for (int b = 0; b < 2; b++) {
            wr2[b] = *(const u64*)&s_wr [c][op * 2 + b];
            wi2[b] = *(const u64*)&s_wi [c][op * 2 + b];
            nw2[b] = *(const u64*)&s_nwi[c][op * 2 + b];
        }
#pragma unroll
        for (int a = 0; a < 2; a++)
#pragma unroll
            for (int b = 0; b < 2; b++) {
                fma2(ar[a][b], xr[a], wr2[b]); fma2(ar[a][b], xi[a], nw2[b]);
                fma2(ai[a][b], xi[a], wr2[b]); fma2(ai[a][b], xr[a], wi2[b]);
            }
    }
#pragma unroll
    for (int a = 0; a < 2; a++)
#pragma unroll
        for (int b = 0; b < 2; b++) {
            int blc = (blp * 2 + a) * NC + op * 2 + b;
            float* gb = g_G + (((size_t)blc * NP + p) * 2) * NJ + jp * 2;
            *(float2*)gb        = up2(ar[a][b]);
            *(float2*)(gb + NJ) = up2(ai[a][b]);
        }
}

// ---------------- inverse H-DFT v3: output-pair fold (h & 128-h), C/S split ----------------
__global__ __launch_bounds__(256) void invH2() {
    __shared__ __align__(16) float SE[2][33][36];
    __shared__ __align__(16) float SD[2][33][36];
    int blo = blockIdx.x, t = threadIdx.x;
    const float* src = g_G + (size_t)blo * NP * 64;
    for (int f = t; f < 33 * 16; f += 256) {
        int r = f >> 4, c4 = (f & 15) * 4;
        int comp = c4 >> 5, cc = c4 & 31;
        float4 a = *(const float4*)(src + r * 64 + c4);
        float4 e, d;
        if (r == 0) {
            e = a; d = make_float4(0.f, 0.f, 0.f, 0.f);
        } else if (r == 32) {
            e = a;
            if (comp == 0) d = make_float4(-a.x, -a.y, -a.z, -a.w);
            else           d = a;
        } else {
            float4 b = *(const float4*)(src + (64 - r) * 64 + c4);
            e = make_float4(a.x + b.x, a.y + b.y, a.z + b.z, a.w + b.w);
            if (comp == 0) d = make_float4(a.x - b.x, a.y - b.y, a.z - b.z, a.w - b.w);
            else           d = make_float4(b.x - a.x, b.y - a.y, b.z - a.z, b.w - a.w);
        }
        *(float4*)&SE[comp][r][cc] = e;
        *(float4*)&SD[comp ^ 1][r][cc] = d;
    }
    __syncthreads();

    int tx = t & 7, ty = t >> 3;
    int compo = tx >> 2, bf = (tx & 3) * 8;
    const float* pe = &SE[compo][0][bf];
    const float* pd = &SD[compo][0][bf];

    u64 cd[2], sd[2], c1[2], s1[2], ns1[2];
#pragma unroll
    for (int i = 0; i < 2; i++) {
        int u = ty * 2 + i;
        float ss, cc2; sincospif((float)u * (1.0f / 64.0f), &ss, &cc2);
        c1[i] = dup2(cc2); s1[i] = dup2(ss); ns1[i] = dup2(-ss);
        cd[i] = dup2(1.0f); sd[i] = dup2(0.0f);
    }
    u64 Cs[2][4], Ss[2][4];
#pragma unroll
    for (int i = 0; i < 2; i++)
#pragma unroll
        for (int m = 0; m < 4; m++) { Cs[i][m] = 0ull; Ss[i][m] = 0ull; }

    for (int r = 0; r < 33; r++) {
        ulonglong2 e01 = *(const ulonglong2*)(pe + r * 36);
        ulonglong2 e23 = *(const ulonglong2*)(pe + r * 36 + 4);
        ulonglong2 d01 = *(const ulonglong2*)(pd + r * 36);
        ulonglong2 d23 = *(const ulonglong2*)(pd + r * 36 + 4);
#pragma unroll
        for (int i = 0; i < 2; i++) {
            fma2(Cs[i][0], cd[i], e01.x); fma2(Cs[i][1], cd[i], e01.y);
            fma2(Cs[i][2], cd[i], e23.x); fma2(Cs[i][3], cd[i], e23.y);
            fma2(Ss[i][0], sd[i], d01.x); fma2(Ss[i][1], sd[i], d01.y);
            fma2(Ss[i][2], sd[i], d23.x); fma2(Ss[i][3], sd[i], d23.y);
            u64 nc = mul2(cd[i], c1[i]); fma2(nc, sd[i], ns1[i]);
            u64 ns = mul2(sd[i], c1[i]); fma2(ns, cd[i], s1[i]);
            cd[i] = nc; sd[i] = ns;
        }
    }
    u64 sc = dup2(1.0f / 128.0f);
    int jb = compo * 32 + (tx & 3) * 8;
#pragma unroll
    for (int i = 0; i < 2; i++) {
        int u = ty * 2 + i;
        u64 lo[4], hi[4];
#pragma unroll
        for (int m = 0; m < 4; m++) {
            lo[m] = mul2(add2(Cs[i][m], Ss[i][m]), sc);
            u64 diff = Cs[i][m]; fma2(diff, dup2(-1.0f), Ss[i][m]);
            hi[m] = mul2(diff, sc);
        }
        float* dlo = g_tmp + ((size_t)blo * NH + u) * 64 + jb;
        *(ulonglong2*)dlo       = make_ulonglong2(lo[0], lo[1]);
        *(ulonglong2*)(dlo + 4) = make_ulonglong2(lo[2], lo[3]);
        if (u > 0) {
            float* dhi = g_tmp + ((size_t)blo * NH + (128 - u)) * 64 + jb;
            *(ulonglong2*)dhi       = make_ulonglong2(hi[0], hi[1]);
            *(ulonglong2*)(dhi + 4) = make_ulonglong2(hi[2], hi[3]);
        }
    }
    if (t < 64) {
        int comp = t >> 5, j = t & 31;
        float s = 0.0f;
#pragma unroll
        for (int r = 0; r < 33; r++) {
            float v = SE[comp][r][j];
            s += (r & 1) ? -v : v;
        }
        g_tmp[((size_t)blo * NH + 64) * 64 + comp * 32 + j] = s * (1.0f / 128.0f);
    }
}

// ---------------- inverse W c2r, mirror-folded ----------------
__global__ __launch_bounds__(256, 2) void gemm_inv(float* __restrict__ out) {
    extern __shared__ __align__(16) float sm[];
    float2* Rr2 = (float2*)sm;               // [32][130]
    float2* Ri2 = Rr2 + 32 * 130;            // [32][130]
    float*  Bc  = (float*)(Ri2 + 32 * 130);  // [32][68]
    float*  Bs  = Bc + 32 * 68;              // [32][68]

    int bx = blockIdx.x;
    int by = blockIdx.y;
    int t = threadIdx.x;
    int tx = t & 15, ty = t >> 4;

    const float* src = g_tmp + (size_t)by * 128 * 64;
#pragma unroll
    for (int q = 0; q < 8; q++) {
        int f = t + 256 * q;
        int row = f >> 4, fc = f & 15;
        float4 v = *(const float4*)(src + (size_t)row * 64 + fc * 4);
        float2* dst = (fc < 8) ? Rr2 : Ri2;
        int kb = (fc & 7) * 4;
        dst[(kb + 0) * 130 + row] = make_float2(v.x, v.x);
        dst[(kb + 1) * 130 + row] = make_float2(v.y, v.y);
        dst[(kb + 2) * 130 + row] = make_float2(v.z, v.z);
        dst[(kb + 3) * 130 + row] = make_float2(v.w, v.w);
    }
#pragma unroll
    for (int q = 0; q < 4; q++) {
        int f = t + 256 * q;
        int arr = f >> 9, rem = f & 511;
        int k = rem >> 4, wl4 = (rem & 15) * 4;
        float4 v = *(const float4*)(g_DI + (size_t)(arr * 32 + k) * 256 + bx * 64 + wl4);
        float* dst = arr ? Bs : Bc;
        *(float4*)&dst[k * 68 + wl4] = v;
    }
    __syncthreads();

    u64 Cc[8][2], Csv[8][2];
#pragma unroll
    for (int i = 0; i < 8; i++)
#pragma unroll
        for (int m = 0; m < 2; m++) { Cc[i][m] = 0ull; Csv[i][m] = 0ull; }

#pragma unroll 8
    for (int k = 0; k < 32; k++) {
        ulonglong2 bc = *(const ulonglong2*)&Bc[k * 68 + tx * 4];
        ulonglong2 bs = *(const ulonglong2*)&Bs[k * 68 + tx * 4];
        const ulonglong2* pr = (const ulonglong2*)&Rr2[k * 130 + ty * 8];
        const ulonglong2* pi = (const ulonglong2*)&Ri2[k * 130 + ty * 8];
        ulonglong2 r01 = pr[0], r23 = pr[1], r45 = pr[2], r67 = pr[3];
        ulonglong2 i01 = pi[0], i23 = pi[1], i45 = pi[2], i67 = pi[3];
        u64 aR[8] = {r01.x, r01.y, r23.x, r23.y, r45.x, r45.y, r67.x, r67.y};
        u64 aI[8] = {i01.x, i01.y, i23.x, i23.y, i45.x, i45.y, i67.x, i67.y};
#pragma unroll
        for (int i = 0; i < 8; i++) {
            fma2(Cc[i][0], aR[i], bc.x);
            fma2(Cc[i][1], aR[i], bc.y);
            fma2(Csv[i][0], aI[i], bs.x);
            fma2(Csv[i][1], aI[i], bs.y);
        }
    }
    u64 P1 = dup2(1.0f), N1 = dup2(-1.0f);
#pragma unroll
    for (int i = 0; i < 8; i++) {
        float* ob = out + (size_t)((size_t)by * 128 + ty * 8 + i) * 256;
#pragma unroll
        for (int m = 0; m < 2; m++) {
            int w0 = bx * 64 + tx * 4 + m * 2;
            u64 lo = Cc[i][m]; fma2(lo, P1, Csv[i][m]);
            u64 hi = Cc[i][m]; fma2(hi, N1, Csv[i][m]);
            *(float2*)&ob[w0] = up2(lo);
            float2 hf = up2(hi);
            if (w0 > 0) ob[256 - w0] = hf.x;
            ob[255 - w0] = hf.y;
        }
    }
}

// ---------------- out[:,128] = Tr . coef ----------------
__global__ __launch_bounds__(256) void out128(float* __restrict__ out) {
    int row = blockIdx.x * 256 + threadIdx.x;
    const float* tr = g_tmp + (size_t)row * 64;
    const float sc = 2.0f / 256.0f;
    float s = 0.0f;
#pragma unroll
    for (int q = 0; q < 8; q++) {
        float4 v = *(const float4*)(tr + q * 4);
        float x0 = (q == 0) ? 0.5f * v.x : v.x;
        s += (x0 - v.y) + (v.z - v.w);
    }
    out[(size_t)row * 256 + 128] = s * sc;
}

// ---------------- host launcher ----------------
extern "C" void kernel_launch(void* const* d_in, const int* in_sizes, int n_in,
                              void* d_out, int out_size) {
    const float* x   = (const float*)d_in[0];
    const float* k   = (const float*)d_in[1];
    const float* w1r = (const float*)d_in[2];
    const float* w1i = (const float*)d_in[3];
    const float* w2r = (const float*)d_in[4];
    const float* w2i = (const float*)d_in[5];
    float* out = (float*)d_out;
    (void)in_sizes; (void)n_in; (void)out_size;

    void *pT, *pZ;
    cudaGetSymbolAddress(&pT, g_T);
    cudaGetSymbolAddress(&pZ, g_Z);

    const int INV_SMEM = (32 * 130 * 2 * 2 + 32 * 68 * 2) * 4;          // 83968 B
    cudaFuncSetAttribute(gemm_inv, cudaFuncAttributeMaxDynamicSharedMemorySize, INV_SMEM);
    // No carveout attributes (R11: they starve L1 for neighboring kernels).

    prep_all<<<dim3(32, 32, 4), 256>>>(w1r, w1i, w2r, w2i);

    // forward W-DFT (mirror-folded) over x + k row-blocks
    gemm_fwd<<<NBATT, 256>>>(x, k, NBAT, (float*)pT);

    // forward H-DFT (parity-folded, 33 iters)
    fwdH2<<<NBATT, 256>>>((const float*)pT, (float*)pZ);

    // transpose Z to mode-major for coalesced mix2 loads
    zT<<<dim3(128, 33), 256>>>();

    // per-mode conv + channel mix (coalesced z loads)
    mix2<<<NP * 16, 256>>>();

    // inverse H-DFT (output-pair folded, C/S split)
    invH2<<<NBAT, 256>>>();

    // inverse W c2r (mirror-folded) -> out, plus the w=128 column
    gemm_inv<<<dim3(2, NBAT), 256, INV_SMEM>>>(out);
    out128<<<512, 256>>>(out);
}